// round 10
// baseline (speedup 1.0000x reference)
#include <cuda_runtime.h>
#include <cuda_fp16.h>
#include <mma.h>
#include <math.h>

#define NATOMS 1048576
#define BMOL   16384
#define DIM    128
#define STEPS  8

// ---------------- scratch (static device arrays only) ----------------
__device__ float  g_carry[BMOL * DIM];
__device__ float  g_mem  [BMOL * DIM];
__device__ int    g_segstart[BMOL + 1];
__device__ __half g_Fh[(size_t)NATOMS * DIM];  // 256 MB fp16 features
__device__ __half g_Wh[256 * 512];             // W hi fp16
__device__ __half g_Wl[256 * 512];             // W residual fp16
// ping-pong GEMM input buffers [carry | readout], hi/lo fp16 split
__device__ __half g_Xh0[BMOL * 256];
__device__ __half g_Xl0[BMOL * 256];
__device__ __half g_Xh1[BMOL * 256];
__device__ __half g_Xl1[BMOL * 256];

__device__ __forceinline__ float fsigmoid(float x) {
    return 1.0f / (1.0f + __expf(-x));
}
__device__ __forceinline__ float ftanh(float x) {
    return 1.0f - 2.0f / (__expf(2.0f * x) + 1.0f);
}

// ---------------- init ----------------
__global__ void init_state() {
    int i = blockIdx.x * blockDim.x + threadIdx.x;
    if (i < BMOL * DIM) { g_carry[i] = 0.f; g_mem[i] = 0.f; }
}

__global__ void seg_start_kernel(const int* __restrict__ idx) {
    int b = blockIdx.x * blockDim.x + threadIdx.x;
    if (b > BMOL) return;
    int lo = 0, hi = NATOMS;
    while (lo < hi) {
        int mid = (lo + hi) >> 1;
        if (idx[mid] < b) lo = mid + 1; else hi = mid;
    }
    g_segstart[b] = lo;
}

__global__ void wsplit_kernel(const float* __restrict__ W) {
    int i = blockIdx.x * blockDim.x + threadIdx.x;
    if (i >= 256 * 512) return;
    float v = W[i];
    __half h = __float2half_rn(v);
    g_Wh[i] = h;
    g_Wl[i] = __float2half_rn(v - __half2float(h));
}

__device__ __forceinline__ void h8_to_f(uint4 p, float* f) {
    float2 f0 = __half22float2(*(__half2*)&p.x);
    float2 f1 = __half22float2(*(__half2*)&p.y);
    float2 f2 = __half22float2(*(__half2*)&p.z);
    float2 f3 = __half22float2(*(__half2*)&p.w);
    f[0] = f0.x; f[1] = f0.y; f[2] = f1.x; f[3] = f1.y;
    f[4] = f2.x; f[5] = f2.y; f[6] = f3.x; f[7] = f3.y;
}

__device__ __forceinline__ void f8_to_hl(const float* a, uint4& hi, uint4& lo) {
    __half2 h0 = __floats2half2_rn(a[0], a[1]);
    __half2 h1 = __floats2half2_rn(a[2], a[3]);
    __half2 h2 = __floats2half2_rn(a[4], a[5]);
    __half2 h3 = __floats2half2_rn(a[6], a[7]);
    float2 g0 = __half22float2(h0), g1 = __half22float2(h1);
    float2 g2 = __half22float2(h2), g3 = __half22float2(h3);
    __half2 l0 = __floats2half2_rn(a[0] - g0.x, a[1] - g0.y);
    __half2 l1 = __floats2half2_rn(a[2] - g1.x, a[3] - g1.y);
    __half2 l2 = __floats2half2_rn(a[4] - g2.x, a[5] - g2.y);
    __half2 l3 = __floats2half2_rn(a[6] - g3.x, a[7] - g3.y);
    hi.x = *(unsigned*)&h0; hi.y = *(unsigned*)&h1;
    hi.z = *(unsigned*)&h2; hi.w = *(unsigned*)&h3;
    lo.x = *(unsigned*)&l0; lo.y = *(unsigned*)&l1;
    lo.z = *(unsigned*)&l2; lo.w = *(unsigned*)&l3;
}

// ---------------- step 0: warp-per-molecule convert + segment mean -----------
__global__ void __launch_bounds__(256) step0_kernel(
    const float4* __restrict__ F4, __half* __restrict__ Xh, __half* __restrict__ Xl) {
    int tid  = threadIdx.x;
    int lane = tid & 31;
    int wid  = tid >> 5;
    int b    = blockIdx.x * 8 + wid;
    if (b >= BMOL) return;

    int half_id = lane >> 4;
    int sub     = lane & 15;

    int s = g_segstart[b];
    int e = g_segstart[b + 1];
    int cnt = e - s;

    uint4* xh = (uint4*)Xh + (size_t)b * 32;
    uint4* xl = (uint4*)Xl + (size_t)b * 32;
    uint4 z4 = make_uint4(0, 0, 0, 0);

    if (cnt <= 0) {
        int o = half_id * 16 + sub;
        xh[o] = z4; xl[o] = z4;
        return;
    }

    float acc[8];
    #pragma unroll
    for (int k = 0; k < 8; k++) acc[k] = 0.f;

    for (int a0 = 0; a0 < cnt; a0 += 2) {
        int a = a0 + half_id;
        if (a < cnt) {
            size_t row = (size_t)(s + a);
            float4 va = F4[row * 32 + sub * 2];
            float4 vb = F4[row * 32 + sub * 2 + 1];
            __half2 h0 = __floats2half2_rn(va.x, va.y);
            __half2 h1 = __floats2half2_rn(va.z, va.w);
            __half2 h2 = __floats2half2_rn(vb.x, vb.y);
            __half2 h3 = __floats2half2_rn(vb.z, vb.w);
            uint4 o;
            o.x = *(unsigned*)&h0; o.y = *(unsigned*)&h1;
            o.z = *(unsigned*)&h2; o.w = *(unsigned*)&h3;
            ((uint4*)g_Fh)[row * 16 + sub] = o;
            acc[0] += va.x; acc[1] += va.y; acc[2] += va.z; acc[3] += va.w;
            acc[4] += vb.x; acc[5] += vb.y; acc[6] += vb.z; acc[7] += vb.w;
        }
    }
    #pragma unroll
    for (int k = 0; k < 8; k++) acc[k] += __shfl_xor_sync(0xffffffffu, acc[k], 16);

    float invc = 1.0f / (float)cnt;
    #pragma unroll
    for (int k = 0; k < 8; k++) acc[k] *= invc;

    if (half_id == 0) {
        xh[sub] = z4; xl[sub] = z4;            // carry = 0
    } else {
        uint4 hi, lo;
        f8_to_hl(acc, hi, lo);
        xh[16 + sub] = hi; xl[16 + sub] = lo;
    }
}

// ---------------- warp-per-molecule attention (deferred group softmax) -------
__global__ void __launch_bounds__(256) attn_kernel(
    float* __restrict__ out, int final_step,
    __half* __restrict__ Xh, __half* __restrict__ Xl) {
    int tid  = threadIdx.x;
    int lane = tid & 31;
    int wid  = tid >> 5;
    int b    = blockIdx.x * 8 + wid;
    if (b >= BMOL) return;

    int half_id = lane >> 4;
    int sub     = lane & 15;

    int s = g_segstart[b];
    int e = g_segstart[b + 1];
    int cnt = e - s;

    const float4* crow = (const float4*)(g_carry + (size_t)b * DIM);
    float4 ca = crow[sub * 2];
    float4 cb = crow[sub * 2 + 1];
    float c8[8] = {ca.x, ca.y, ca.z, ca.w, cb.x, cb.y, cb.z, cb.w};

    float m = -INFINITY, ssum = 0.f;
    float acc[8];
    #pragma unroll
    for (int k = 0; k < 8; k++) acc[k] = 0.f;

    const uint4* F4h = (const uint4*)g_Fh;

    if (cnt > 0) {
        int cnt8 = cnt & ~7;
        int a0 = 0;
        for (; a0 < cnt8; a0 += 8) {
            float f[4][8], v[4];
            #pragma unroll
            for (int j = 0; j < 4; j++) {
                int a = a0 + 2 * j + half_id;
                uint4 p = F4h[(size_t)(s + a) * 16 + sub];
                h8_to_f(p, f[j]);
                float vv = 0.f;
                #pragma unroll
                for (int k = 0; k < 8; k++) vv += f[j][k] * c8[k];
                v[j] = vv;
            }
            #pragma unroll
            for (int j = 0; j < 4; j++) {
                #pragma unroll
                for (int o = 8; o > 0; o >>= 1)
                    v[j] += __shfl_xor_sync(0xffffffffu, v[j], o);
            }
            float gm = fmaxf(fmaxf(v[0], v[1]), fmaxf(v[2], v[3]));
            float nm = fmaxf(m, gm);
            float scl = __expf(m - nm);            // 0 on first group (m=-inf)
            float p0 = __expf(v[0] - nm);
            float p1 = __expf(v[1] - nm);
            float p2 = __expf(v[2] - nm);
            float p3 = __expf(v[3] - nm);
            ssum = ssum * scl + ((p0 + p1) + (p2 + p3));
            #pragma unroll
            for (int k = 0; k < 8; k++) {
                float t = acc[k] * scl;
                t += p0 * f[0][k];
                t += p1 * f[1][k];
                t += p2 * f[2][k];
                t += p3 * f[3][k];
                acc[k] = t;
            }
            m = nm;
        }
        for (; a0 < cnt; a0 += 2) {
            int a = a0 + half_id;
            bool valid = (a < cnt);
            float v = 0.f, f[8];
            if (valid) {
                uint4 p = F4h[(size_t)(s + a) * 16 + sub];
                h8_to_f(p, f);
                #pragma unroll
                for (int k = 0; k < 8; k++) v += f[k] * c8[k];
            }
            #pragma unroll
            for (int o = 8; o > 0; o >>= 1) v += __shfl_xor_sync(0xffffffffu, v, o);
            if (valid) {
                float nm   = fmaxf(m, v);
                float scl  = __expf(m - nm);
                float pexp = __expf(v - nm);
                ssum = ssum * scl + pexp;
                #pragma unroll
                for (int k = 0; k < 8; k++) acc[k] = acc[k] * scl + pexp * f[k];
                m = nm;
            }
        }

        // combine half-warps
        float m_o = __shfl_xor_sync(0xffffffffu, m, 16);
        float s_o = __shfl_xor_sync(0xffffffffu, ssum, 16);
        float M2  = fmaxf(m, m_o);
        float sa  = (m   > -INFINITY) ? __expf(m   - M2) : 0.f;
        float sb  = (m_o > -INFINITY) ? __expf(m_o - M2) : 0.f;
        float S    = ssum * sa + s_o * sb;
        float invS = 1.0f / S;
        #pragma unroll
        for (int k = 0; k < 8; k++) {
            float ao = __shfl_xor_sync(0xffffffffu, acc[k], 16);
            acc[k] = (acc[k] * sa + ao * sb) * invS;
        }
    }

    if (final_step) {
        float4* orow = (float4*)(out + (size_t)b * 2 * DIM);
        if (half_id == 0) {
            orow[sub * 2]     = ca;
            orow[sub * 2 + 1] = cb;
        } else {
            orow[32 + sub * 2]     = make_float4(acc[0], acc[1], acc[2], acc[3]);
            orow[32 + sub * 2 + 1] = make_float4(acc[4], acc[5], acc[6], acc[7]);
        }
    } else if (half_id == 1) {
        uint4 hi, lo;
        f8_to_hl(acc, hi, lo);
        ((uint4*)Xh)[(size_t)b * 32 + 16 + sub] = hi;
        ((uint4*)Xl)[(size_t)b * 32 + 16 + sub] = lo;
    }
}

// ---------------- fused cp.async GEMM + LSTM epilogue ------------------------
// Reads X_in (prev step), writes new carry into X_out (ping-pong, race-free).
using namespace nvcuda;
#define GEMM_THREADS 256
#define A_LDH 40
#define B_LDH 136
#define AH_SZ (128 * A_LDH)
#define BH_SZ (32 * B_LDH)
#define STAGE_HALVES (2 * AH_SZ + 2 * BH_SZ)
#define Z_LD 132
#define GEMM_SMEM ((2 * STAGE_HALVES * (int)sizeof(__half)) > (128 * Z_LD * (int)sizeof(float)) ? \
                   (2 * STAGE_HALVES * (int)sizeof(__half)) : (128 * Z_LD * (int)sizeof(float)))

__device__ __forceinline__ void cp16(void* smem, const void* gmem) {
    unsigned saddr = (unsigned)__cvta_generic_to_shared(smem);
    asm volatile("cp.async.cg.shared.global [%0], [%1], 16;" :: "r"(saddr), "l"(gmem));
}

__global__ void __launch_bounds__(GEMM_THREADS, 2) gemm_lstm_kernel(
    const float* __restrict__ bias,
    const __half* __restrict__ Xh_in, const __half* __restrict__ Xl_in,
    __half* __restrict__ Xh_out, __half* __restrict__ Xl_out) {
    int bm = blockIdx.x * 128;
    int jb = blockIdx.y;               // 0..3
    int tid = threadIdx.x;

    extern __shared__ __half smh[];

    wmma::fragment<wmma::accumulator, 16, 16, 16, float> acc[2][4];
    #pragma unroll
    for (int i = 0; i < 2; i++)
        #pragma unroll
        for (int j = 0; j < 4; j++) wmma::fill_fragment(acc[i][j], 0.f);

    int wid = tid >> 5;
    int wm = (wid >> 1) * 32;
    int wn = (wid & 1) * 64;

    auto load_stage = [&](int stg, int k0) {
        __half* Ah = smh + stg * STAGE_HALVES;
        __half* Al = Ah + AH_SZ;
        __half* Bh = Al + AH_SZ;
        __half* Bl = Bh + BH_SZ;
        #pragma unroll
        for (int i = tid; i < 512; i += GEMM_THREADS) {   // A: 128x32 halves
            int r = i >> 2, c = i & 3;
            size_t g = (size_t)(bm + r) * 256 + k0 + c * 8;
            cp16(Ah + r * A_LDH + c * 8, Xh_in + g);
            cp16(Al + r * A_LDH + c * 8, Xl_in + g);
        }
        #pragma unroll
        for (int i = tid; i < 512; i += GEMM_THREADS) {   // B: 32x128 permuted cols
            int r = i >> 4, c = i & 15;
            int gate = c >> 2, j4 = c & 3;
            size_t g = (size_t)(k0 + r) * 512 + gate * 128 + jb * 32 + j4 * 8;
            cp16(Bh + r * B_LDH + c * 8, g_Wh + g);
            cp16(Bl + r * B_LDH + c * 8, g_Wl + g);
        }
        asm volatile("cp.async.commit_group;");
    };

    load_stage(0, 0);

    for (int ks = 0; ks < 8; ks++) {
        if (ks < 7) {
            load_stage((ks + 1) & 1, (ks + 1) * 32);
            asm volatile("cp.async.wait_group 1;");
        } else {
            asm volatile("cp.async.wait_group 0;");
        }
        __syncthreads();

        __half* Ah = smh + (ks & 1) * STAGE_HALVES;
        __half* Al = Ah + AH_SZ;
        __half* Bh = Al + AH_SZ;
        __half* Bl = Bh + BH_SZ;

        #pragma unroll
        for (int kk = 0; kk < 32; kk += 16) {
            wmma::fragment<wmma::matrix_a, 16, 16, 16, __half, wmma::row_major> ah[2], al[2];
            wmma::fragment<wmma::matrix_b, 16, 16, 16, __half, wmma::row_major> bh[4], bl[4];
            #pragma unroll
            for (int i = 0; i < 2; i++) {
                wmma::load_matrix_sync(ah[i], &Ah[(wm + i * 16) * A_LDH + kk], A_LDH);
                wmma::load_matrix_sync(al[i], &Al[(wm + i * 16) * A_LDH + kk], A_LDH);
            }
            #pragma unroll
            for (int j = 0; j < 4; j++) {
                wmma::load_matrix_sync(bh[j], &Bh[kk * B_LDH + wn + j * 16], B_LDH);
                wmma::load_matrix_sync(bl[j], &Bl[kk * B_LDH + wn + j * 16], B_LDH);
            }
            #pragma unroll
            for (int i = 0; i < 2; i++)
                #pragma unroll
                for (int j = 0; j < 4; j++) {
                    wmma::mma_sync(acc[i][j], ah[i], bh[j], acc[i][j]);
                    wmma::mma_sync(acc[i][j], ah[i], bl[j], acc[i][j]);
                    wmma::mma_sync(acc[i][j], al[i], bh[j], acc[i][j]);
                }
        }
        __syncthreads();
    }

    // stage z tile in SMEM (aliases the cp.async stage buffers; mainloop done)
    float* zbuf = (float*)smh;
    #pragma unroll
    for (int i = 0; i < 2; i++)
        #pragma unroll
        for (int j = 0; j < 4; j++)
            wmma::store_matrix_sync(&zbuf[(wm + i * 16) * Z_LD + wn + j * 16],
                                    acc[i][j], Z_LD, wmma::mem_row_major);
    __syncthreads();

    // LSTM epilogue: 128 rows x 32 j's
    #pragma unroll
    for (int p = tid; p < 128 * 32; p += GEMM_THREADS) {
        int r  = p >> 5;
        int jj = p & 31;
        int j  = jb * 32 + jj;
        float u = zbuf[r * Z_LD + jj]      + bias[j];
        float f = zbuf[r * Z_LD + 32 + jj] + bias[128 + j];
        float c = zbuf[r * Z_LD + 64 + jj] + bias[256 + j];
        float o = zbuf[r * Z_LD + 96 + jj] + bias[384 + j];
        float su = fsigmoid(u);
        float sf = fsigmoid(f);
        float so = fsigmoid(o);
        size_t gi = (size_t)(bm + r) * DIM + j;
        float mem = sf * g_mem[gi] + su * ftanh(c);
        g_mem[gi] = mem;
        float cy  = so * ftanh(mem);
        g_carry[gi] = cy;
        // hi/lo fp16 carry into the OUTPUT ping-pong buffer (race-free)
        __half h = __float2half_rn(cy);
        size_t xi = (size_t)(bm + r) * 256 + j;
        Xh_out[xi] = h;
        Xl_out[xi] = __float2half_rn(cy - __half2float(h));
    }
}

// ---------------- launch ----------------
extern "C" void kernel_launch(void* const* d_in, const int* in_sizes, int n_in,
                              void* d_out, int out_size) {
    const float* F    = (const float*)d_in[0];
    const int*   idx  = (const int*)d_in[1];
    const float* W    = (const float*)d_in[2];
    const float* bias = (const float*)d_in[3];
    float* out = (float*)d_out;

    static bool attr_done = false;
    if (!attr_done) {
        cudaFuncSetAttribute(gemm_lstm_kernel, cudaFuncAttributeMaxDynamicSharedMemorySize,
                             (int)GEMM_SMEM);
        attr_done = true;
    }

    void *xh0p, *xl0p, *xh1p, *xl1p;
    cudaGetSymbolAddress(&xh0p, g_Xh0);
    cudaGetSymbolAddress(&xl0p, g_Xl0);
    cudaGetSymbolAddress(&xh1p, g_Xh1);
    cudaGetSymbolAddress(&xl1p, g_Xl1);
    __half* Xh[2] = {(__half*)xh0p, (__half*)xh1p};
    __half* Xl[2] = {(__half*)xl0p, (__half*)xl1p};

    init_state<<<(BMOL * DIM + 255) / 256, 256>>>();
    seg_start_kernel<<<(BMOL + 1 + 255) / 256, 256>>>(idx);
    wsplit_kernel<<<(256 * 512 + 255) / 256, 256>>>(W);

    dim3 gg(BMOL / 128, 4);

    // t = 0: convert + mean readout (carry == 0) -> X[0]
    step0_kernel<<<BMOL / 8, 256>>>((const float4*)F, Xh[0], Xl[0]);

    for (int t = 0; t < STEPS - 1; t++) {
        int cur = t & 1, nxt = (t + 1) & 1;
        // GEMM+LSTM on X[cur]; new carry -> X[nxt] (and fp32 g_carry/g_mem)
        gemm_lstm_kernel<<<gg, GEMM_THREADS, GEMM_SMEM>>>(
            bias, Xh[cur], Xl[cur], Xh[nxt], Xl[nxt]);
        // attention step t+1: readout -> X[nxt] (or final output)
        attn_kernel<<<BMOL / 8, 256>>>(out, (t == STEPS - 2) ? 1 : 0, Xh[nxt], Xl[nxt]);
    }
}

// round 11
// speedup vs baseline: 1.0819x; 1.0819x over previous
#include <cuda_runtime.h>
#include <cuda_fp16.h>
#include <mma.h>
#include <math.h>

#define NATOMS 1048576
#define BMOL   16384
#define DIM    128
#define STEPS  8

// ---------------- scratch (static device arrays only) ----------------
__device__ float  g_carry[BMOL * DIM];
__device__ float  g_mem  [BMOL * DIM];
__device__ float  g_z    [BMOL * 4 * DIM];
__device__ int    g_segstart[BMOL + 1];
__device__ __half g_Fh[(size_t)NATOMS * DIM];  // 256 MB fp16 features
__device__ __half g_Wh[256 * 512];             // W hi fp16
__device__ __half g_Wl[256 * 512];             // W residual fp16
__device__ __half g_Xh[BMOL * 256];            // GEMM input hi fp16  [carry|readout]
__device__ __half g_Xl[BMOL * 256];            // GEMM input lo fp16

__device__ __forceinline__ float fsigmoid(float x) {
    return 1.0f / (1.0f + __expf(-x));
}
__device__ __forceinline__ float ftanh(float x) {
    return 1.0f - 2.0f / (__expf(2.0f * x) + 1.0f);
}

// ---------------- init ----------------
__global__ void init_state() {
    int i = blockIdx.x * blockDim.x + threadIdx.x;
    if (i < BMOL * DIM) { g_carry[i] = 0.f; g_mem[i] = 0.f; }
}

__global__ void seg_start_kernel(const int* __restrict__ idx) {
    int b = blockIdx.x * blockDim.x + threadIdx.x;
    if (b > BMOL) return;
    int lo = 0, hi = NATOMS;
    while (lo < hi) {
        int mid = (lo + hi) >> 1;
        if (idx[mid] < b) lo = mid + 1; else hi = mid;
    }
    g_segstart[b] = lo;
}

__global__ void wsplit_kernel(const float* __restrict__ W) {
    int i = blockIdx.x * blockDim.x + threadIdx.x;
    if (i >= 256 * 512) return;
    float v = W[i];
    __half h = __float2half_rn(v);
    g_Wh[i] = h;
    g_Wl[i] = __float2half_rn(v - __half2float(h));
}

__device__ __forceinline__ void h8_to_f(uint4 p, float* f) {
    float2 f0 = __half22float2(*(__half2*)&p.x);
    float2 f1 = __half22float2(*(__half2*)&p.y);
    float2 f2 = __half22float2(*(__half2*)&p.z);
    float2 f3 = __half22float2(*(__half2*)&p.w);
    f[0] = f0.x; f[1] = f0.y; f[2] = f1.x; f[3] = f1.y;
    f[4] = f2.x; f[5] = f2.y; f[6] = f3.x; f[7] = f3.y;
}

__device__ __forceinline__ void f8_to_hl(const float* a, uint4& hi, uint4& lo) {
    __half2 h0 = __floats2half2_rn(a[0], a[1]);
    __half2 h1 = __floats2half2_rn(a[2], a[3]);
    __half2 h2 = __floats2half2_rn(a[4], a[5]);
    __half2 h3 = __floats2half2_rn(a[6], a[7]);
    float2 g0 = __half22float2(h0), g1 = __half22float2(h1);
    float2 g2 = __half22float2(h2), g3 = __half22float2(h3);
    __half2 l0 = __floats2half2_rn(a[0] - g0.x, a[1] - g0.y);
    __half2 l1 = __floats2half2_rn(a[2] - g1.x, a[3] - g1.y);
    __half2 l2 = __floats2half2_rn(a[4] - g2.x, a[5] - g2.y);
    __half2 l3 = __floats2half2_rn(a[6] - g3.x, a[7] - g3.y);
    hi.x = *(unsigned*)&h0; hi.y = *(unsigned*)&h1;
    hi.z = *(unsigned*)&h2; hi.w = *(unsigned*)&h3;
    lo.x = *(unsigned*)&l0; lo.y = *(unsigned*)&l1;
    lo.z = *(unsigned*)&l2; lo.w = *(unsigned*)&l3;
}

// ---------------- step 0: warp-per-molecule convert + segment mean -----------
__global__ void __launch_bounds__(256) step0_kernel(const float4* __restrict__ F4) {
    int tid  = threadIdx.x;
    int lane = tid & 31;
    int wid  = tid >> 5;
    int b    = blockIdx.x * 8 + wid;
    if (b >= BMOL) return;

    int half_id = lane >> 4;
    int sub     = lane & 15;

    int s = g_segstart[b];
    int e = g_segstart[b + 1];
    int cnt = e - s;

    uint4* xh = (uint4*)g_Xh + (size_t)b * 32;
    uint4* xl = (uint4*)g_Xl + (size_t)b * 32;
    uint4 z4 = make_uint4(0, 0, 0, 0);

    if (cnt <= 0) {
        int o = half_id * 16 + sub;
        xh[o] = z4; xl[o] = z4;
        return;
    }

    float acc[8];
    #pragma unroll
    for (int k = 0; k < 8; k++) acc[k] = 0.f;

    for (int a0 = 0; a0 < cnt; a0 += 2) {
        int a = a0 + half_id;
        if (a < cnt) {
            size_t row = (size_t)(s + a);
            float4 va = F4[row * 32 + sub * 2];
            float4 vb = F4[row * 32 + sub * 2 + 1];
            __half2 h0 = __floats2half2_rn(va.x, va.y);
            __half2 h1 = __floats2half2_rn(va.z, va.w);
            __half2 h2 = __floats2half2_rn(vb.x, vb.y);
            __half2 h3 = __floats2half2_rn(vb.z, vb.w);
            uint4 o;
            o.x = *(unsigned*)&h0; o.y = *(unsigned*)&h1;
            o.z = *(unsigned*)&h2; o.w = *(unsigned*)&h3;
            ((uint4*)g_Fh)[row * 16 + sub] = o;
            acc[0] += va.x; acc[1] += va.y; acc[2] += va.z; acc[3] += va.w;
            acc[4] += vb.x; acc[5] += vb.y; acc[6] += vb.z; acc[7] += vb.w;
        }
    }
    #pragma unroll
    for (int k = 0; k < 8; k++) acc[k] += __shfl_xor_sync(0xffffffffu, acc[k], 16);

    float invc = 1.0f / (float)cnt;
    #pragma unroll
    for (int k = 0; k < 8; k++) acc[k] *= invc;

    if (half_id == 0) {
        xh[sub] = z4; xl[sub] = z4;            // carry = 0
    } else {
        uint4 hi, lo;
        f8_to_hl(acc, hi, lo);
        xh[16 + sub] = hi; xl[16 + sub] = lo;
    }
}

// ---------------- warp-per-molecule attention (deferred group softmax) -------
__global__ void __launch_bounds__(256) attn_kernel(float* __restrict__ out, int final_step) {
    int tid  = threadIdx.x;
    int lane = tid & 31;
    int wid  = tid >> 5;
    int b    = blockIdx.x * 8 + wid;
    if (b >= BMOL) return;

    int half_id = lane >> 4;
    int sub     = lane & 15;

    int s = g_segstart[b];
    int e = g_segstart[b + 1];
    int cnt = e - s;

    const float4* crow = (const float4*)(g_carry + (size_t)b * DIM);
    float4 ca = crow[sub * 2];
    float4 cb = crow[sub * 2 + 1];
    float c8[8] = {ca.x, ca.y, ca.z, ca.w, cb.x, cb.y, cb.z, cb.w};

    float m = -INFINITY, ssum = 0.f;
    float acc[8];
    #pragma unroll
    for (int k = 0; k < 8; k++) acc[k] = 0.f;

    const uint4* F4h = (const uint4*)g_Fh;

    if (cnt > 0) {
        int cnt8 = cnt & ~7;
        int a0 = 0;
        for (; a0 < cnt8; a0 += 8) {
            float f[4][8], v[4];
            #pragma unroll
            for (int j = 0; j < 4; j++) {
                int a = a0 + 2 * j + half_id;
                uint4 p = F4h[(size_t)(s + a) * 16 + sub];
                h8_to_f(p, f[j]);
                float vv = 0.f;
                #pragma unroll
                for (int k = 0; k < 8; k++) vv += f[j][k] * c8[k];
                v[j] = vv;
            }
            #pragma unroll
            for (int j = 0; j < 4; j++) {
                #pragma unroll
                for (int o = 8; o > 0; o >>= 1)
                    v[j] += __shfl_xor_sync(0xffffffffu, v[j], o);
            }
            // deferred group softmax (one rescale per 4 scores)
            float gm = fmaxf(fmaxf(v[0], v[1]), fmaxf(v[2], v[3]));
            float nm = fmaxf(m, gm);
            float scl = __expf(m - nm);            // 0 on first group (m=-inf)
            float p0 = __expf(v[0] - nm);
            float p1 = __expf(v[1] - nm);
            float p2 = __expf(v[2] - nm);
            float p3 = __expf(v[3] - nm);
            ssum = ssum * scl + ((p0 + p1) + (p2 + p3));
            #pragma unroll
            for (int k = 0; k < 8; k++) {
                float t = acc[k] * scl;
                t += p0 * f[0][k];
                t += p1 * f[1][k];
                t += p2 * f[2][k];
                t += p3 * f[3][k];
                acc[k] = t;
            }
            m = nm;
        }
        for (; a0 < cnt; a0 += 2) {
            int a = a0 + half_id;
            bool valid = (a < cnt);
            float v = 0.f, f[8];
            if (valid) {
                uint4 p = F4h[(size_t)(s + a) * 16 + sub];
                h8_to_f(p, f);
                #pragma unroll
                for (int k = 0; k < 8; k++) v += f[k] * c8[k];
            }
            #pragma unroll
            for (int o = 8; o > 0; o >>= 1) v += __shfl_xor_sync(0xffffffffu, v, o);
            if (valid) {
                float nm   = fmaxf(m, v);
                float scl  = __expf(m - nm);
                float pexp = __expf(v - nm);
                ssum = ssum * scl + pexp;
                #pragma unroll
                for (int k = 0; k < 8; k++) acc[k] = acc[k] * scl + pexp * f[k];
                m = nm;
            }
        }

        // combine half-warps
        float m_o = __shfl_xor_sync(0xffffffffu, m, 16);
        float s_o = __shfl_xor_sync(0xffffffffu, ssum, 16);
        float M2  = fmaxf(m, m_o);
        float sa  = (m   > -INFINITY) ? __expf(m   - M2) : 0.f;
        float sb  = (m_o > -INFINITY) ? __expf(m_o - M2) : 0.f;
        float S    = ssum * sa + s_o * sb;
        float invS = 1.0f / S;
        #pragma unroll
        for (int k = 0; k < 8; k++) {
            float ao = __shfl_xor_sync(0xffffffffu, acc[k], 16);
            acc[k] = (acc[k] * sa + ao * sb) * invS;
        }
    }

    if (final_step) {
        float4* orow = (float4*)(out + (size_t)b * 2 * DIM);
        if (half_id == 0) {
            orow[sub * 2]     = ca;
            orow[sub * 2 + 1] = cb;
        } else {
            orow[32 + sub * 2]     = make_float4(acc[0], acc[1], acc[2], acc[3]);
            orow[32 + sub * 2 + 1] = make_float4(acc[4], acc[5], acc[6], acc[7]);
        }
    } else if (half_id == 1) {
        uint4 hi, lo;
        f8_to_hl(acc, hi, lo);
        ((uint4*)g_Xh)[(size_t)b * 32 + 16 + sub] = hi;
        ((uint4*)g_Xl)[(size_t)b * 32 + 16 + sub] = lo;
    }
}

// ---------------- cp.async pipelined fp16-split GEMM -------------------------
// g_z = X[BMOL,256] @ W[256,512]; X,W pre-split hi/lo fp16; fp32 accumulate.
using namespace nvcuda;
#define GEMM_THREADS 256
#define A_LDH 40
#define B_LDH 136
#define AH_SZ (128 * A_LDH)
#define BH_SZ (32 * B_LDH)
#define STAGE_HALVES (2 * AH_SZ + 2 * BH_SZ)
#define GEMM_SMEM (2 * STAGE_HALVES * sizeof(__half))

__device__ __forceinline__ void cp16(void* smem, const void* gmem) {
    unsigned saddr = (unsigned)__cvta_generic_to_shared(smem);
    asm volatile("cp.async.cg.shared.global [%0], [%1], 16;" :: "r"(saddr), "l"(gmem));
}

__global__ void __launch_bounds__(GEMM_THREADS, 2) gemm_kernel() {
    int bm = blockIdx.x * 128;
    int bn = blockIdx.y * 128;
    int tid = threadIdx.x;

    extern __shared__ __half smh[];

    wmma::fragment<wmma::accumulator, 16, 16, 16, float> acc[2][4];
    #pragma unroll
    for (int i = 0; i < 2; i++)
        #pragma unroll
        for (int j = 0; j < 4; j++) wmma::fill_fragment(acc[i][j], 0.f);

    int wid = tid >> 5;
    int wm = (wid >> 1) * 32;
    int wn = (wid & 1) * 64;

    auto load_stage = [&](int stg, int k0) {
        __half* Ah = smh + stg * STAGE_HALVES;
        __half* Al = Ah + AH_SZ;
        __half* Bh = Al + AH_SZ;
        __half* Bl = Bh + BH_SZ;
        #pragma unroll
        for (int i = tid; i < 512; i += GEMM_THREADS) {   // A: 128x32 halves
            int r = i >> 2, c = i & 3;
            size_t g = (size_t)(bm + r) * 256 + k0 + c * 8;
            cp16(Ah + r * A_LDH + c * 8, g_Xh + g);
            cp16(Al + r * A_LDH + c * 8, g_Xl + g);
        }
        #pragma unroll
        for (int i = tid; i < 512; i += GEMM_THREADS) {   // B: 32x128 halves
            int r = i >> 4, c = i & 15;
            size_t g = (size_t)(k0 + r) * 512 + bn + c * 8;
            cp16(Bh + r * B_LDH + c * 8, g_Wh + g);
            cp16(Bl + r * B_LDH + c * 8, g_Wl + g);
        }
        asm volatile("cp.async.commit_group;");
    };

    load_stage(0, 0);

    for (int ks = 0; ks < 8; ks++) {
        if (ks < 7) {
            load_stage((ks + 1) & 1, (ks + 1) * 32);
            asm volatile("cp.async.wait_group 1;");
        } else {
            asm volatile("cp.async.wait_group 0;");
        }
        __syncthreads();

        __half* Ah = smh + (ks & 1) * STAGE_HALVES;
        __half* Al = Ah + AH_SZ;
        __half* Bh = Al + AH_SZ;
        __half* Bl = Bh + BH_SZ;

        #pragma unroll
        for (int kk = 0; kk < 32; kk += 16) {
            wmma::fragment<wmma::matrix_a, 16, 16, 16, __half, wmma::row_major> ah[2], al[2];
            wmma::fragment<wmma::matrix_b, 16, 16, 16, __half, wmma::row_major> bh[4], bl[4];
            #pragma unroll
            for (int i = 0; i < 2; i++) {
                wmma::load_matrix_sync(ah[i], &Ah[(wm + i * 16) * A_LDH + kk], A_LDH);
                wmma::load_matrix_sync(al[i], &Al[(wm + i * 16) * A_LDH + kk], A_LDH);
            }
            #pragma unroll
            for (int j = 0; j < 4; j++) {
                wmma::load_matrix_sync(bh[j], &Bh[kk * B_LDH + wn + j * 16], B_LDH);
                wmma::load_matrix_sync(bl[j], &Bl[kk * B_LDH + wn + j * 16], B_LDH);
            }
            #pragma unroll
            for (int i = 0; i < 2; i++)
                #pragma unroll
                for (int j = 0; j < 4; j++) {
                    wmma::mma_sync(acc[i][j], ah[i], bh[j], acc[i][j]);
                    wmma::mma_sync(acc[i][j], ah[i], bl[j], acc[i][j]);
                    wmma::mma_sync(acc[i][j], al[i], bh[j], acc[i][j]);
                }
        }
        __syncthreads();
    }

    #pragma unroll
    for (int i = 0; i < 2; i++)
        #pragma unroll
        for (int j = 0; j < 4; j++)
            wmma::store_matrix_sync(&g_z[(size_t)(bm + wm + i * 16) * 512 + bn + wn + j * 16],
                                    acc[i][j], 512, wmma::mem_row_major);
}

// ---------------- LSTM pointwise (writes fp32 carry + X carry halves) --------
__global__ void lstm_kernel(const float4* __restrict__ bias4) {
    int p = blockIdx.x * blockDim.x + threadIdx.x;
    if (p >= BMOL * 32) return;
    int b = p >> 5;
    int q = p & 31;
    const float4* zr = (const float4*)(g_z + (size_t)b * 512);
    float4 u4 = zr[q];
    float4 f4 = zr[32 + q];
    float4 c4 = zr[64 + q];
    float4 o4 = zr[96 + q];
    float4 bu = bias4[q], bf = bias4[32 + q], bc = bias4[64 + q], bo = bias4[96 + q];
    float4 m4 = ((const float4*)g_mem)[(size_t)b * 32 + q];

    float un[4] = {u4.x + bu.x, u4.y + bu.y, u4.z + bu.z, u4.w + bu.w};
    float fn[4] = {f4.x + bf.x, f4.y + bf.y, f4.z + bf.z, f4.w + bf.w};
    float cn[4] = {c4.x + bc.x, c4.y + bc.y, c4.z + bc.z, c4.w + bc.w};
    float on[4] = {o4.x + bo.x, o4.y + bo.y, o4.z + bo.z, o4.w + bo.w};
    float mm[4] = {m4.x, m4.y, m4.z, m4.w};
    float nm[4], cy[4];
    #pragma unroll
    for (int k = 0; k < 4; k++) {
        float su = fsigmoid(un[k]);
        float sf = fsigmoid(fn[k]);
        float so = fsigmoid(on[k]);
        nm[k] = sf * mm[k] + su * ftanh(cn[k]);
        cy[k] = so * ftanh(nm[k]);
    }
    ((float4*)g_mem)[(size_t)b * 32 + q]   = make_float4(nm[0], nm[1], nm[2], nm[3]);
    ((float4*)g_carry)[(size_t)b * 32 + q] = make_float4(cy[0], cy[1], cy[2], cy[3]);

    // hi/lo fp16 carry into X row (dims q*4..q*4+3)
    __half2 h01 = __floats2half2_rn(cy[0], cy[1]);
    __half2 h23 = __floats2half2_rn(cy[2], cy[3]);
    float2 g01 = __half22float2(h01), g23 = __half22float2(h23);
    __half2 l01 = __floats2half2_rn(cy[0] - g01.x, cy[1] - g01.y);
    __half2 l23 = __floats2half2_rn(cy[2] - g23.x, cy[3] - g23.y);
    uint2 hv, lv;
    hv.x = *(unsigned*)&h01; hv.y = *(unsigned*)&h23;
    lv.x = *(unsigned*)&l01; lv.y = *(unsigned*)&l23;
    ((uint2*)(g_Xh + (size_t)b * 256))[q] = hv;
    ((uint2*)(g_Xl + (size_t)b * 256))[q] = lv;
}

// ---------------- launch ----------------
extern "C" void kernel_launch(void* const* d_in, const int* in_sizes, int n_in,
                              void* d_out, int out_size) {
    const float* F    = (const float*)d_in[0];
    const int*   idx  = (const int*)d_in[1];
    const float* W    = (const float*)d_in[2];
    const float* bias = (const float*)d_in[3];
    float* out = (float*)d_out;

    static bool attr_done = false;
    if (!attr_done) {
        cudaFuncSetAttribute(gemm_kernel, cudaFuncAttributeMaxDynamicSharedMemorySize,
                             (int)GEMM_SMEM);
        attr_done = true;
    }

    init_state<<<(BMOL * DIM + 255) / 256, 256>>>();
    seg_start_kernel<<<(BMOL + 1 + 255) / 256, 256>>>(idx);
    wsplit_kernel<<<(256 * 512 + 255) / 256, 256>>>(W);

    dim3 gg(BMOL / 128, 4);

    // t = 0: convert + mean readout (carry == 0)
    step0_kernel<<<BMOL / 8, 256>>>((const float4*)F);
    gemm_kernel<<<gg, GEMM_THREADS, GEMM_SMEM>>>();
    lstm_kernel<<<(BMOL * 32 + 255) / 256, 256>>>((const float4*)bias);

    for (int t = 1; t < STEPS; t++) {
        attn_kernel<<<BMOL / 8, 256>>>(out, (t == STEPS - 1) ? 1 : 0);
        if (t < STEPS - 1) {
            gemm_kernel<<<gg, GEMM_THREADS, GEMM_SMEM>>>();
            lstm_kernel<<<(BMOL * 32 + 255) / 256, 256>>>((const float4*)bias);
        }
    }
}

// round 12
// speedup vs baseline: 1.1277x; 1.0423x over previous
#include <cuda_runtime.h>
#include <cuda_fp16.h>
#include <mma.h>
#include <math.h>

#define NATOMS 1048576
#define BMOL   16384
#define DIM    128
#define STEPS  8

// ---------------- scratch (static device arrays only) ----------------
__device__ float  g_mem  [BMOL * DIM];
__device__ float  g_z    [BMOL * 4 * DIM];
__device__ int    g_segstart[BMOL + 1];
__device__ __half g_Fh[(size_t)NATOMS * DIM];  // 256 MB fp16 features
__device__ __half g_Wh[256 * 512];             // W hi fp16
__device__ __half g_Wl[256 * 512];             // W residual fp16
__device__ __half g_Xh[BMOL * 256];            // GEMM input hi fp16  [carry|readout]
__device__ __half g_Xl[BMOL * 256];            // GEMM input lo fp16

__device__ __forceinline__ float fsigmoid(float x) {
    return 1.0f / (1.0f + __expf(-x));
}
__device__ __forceinline__ float ftanh(float x) {
    return 1.0f - 2.0f / (__expf(2.0f * x) + 1.0f);
}

// ---------------- init ----------------
__global__ void init_state() {
    int i = blockIdx.x * blockDim.x + threadIdx.x;
    if (i < BMOL * DIM) g_mem[i] = 0.f;
}

__global__ void seg_start_kernel(const int* __restrict__ idx) {
    int b = blockIdx.x * blockDim.x + threadIdx.x;
    if (b > BMOL) return;
    int lo = 0, hi = NATOMS;
    while (lo < hi) {
        int mid = (lo + hi) >> 1;
        if (idx[mid] < b) lo = mid + 1; else hi = mid;
    }
    g_segstart[b] = lo;
}

__global__ void wsplit_kernel(const float* __restrict__ W) {
    int i = blockIdx.x * blockDim.x + threadIdx.x;
    if (i >= 256 * 512) return;
    float v = W[i];
    __half h = __float2half_rn(v);
    g_Wh[i] = h;
    g_Wl[i] = __float2half_rn(v - __half2float(h));
}

__device__ __forceinline__ void h8_to_f(uint4 p, float* f) {
    float2 f0 = __half22float2(*(__half2*)&p.x);
    float2 f1 = __half22float2(*(__half2*)&p.y);
    float2 f2 = __half22float2(*(__half2*)&p.z);
    float2 f3 = __half22float2(*(__half2*)&p.w);
    f[0] = f0.x; f[1] = f0.y; f[2] = f1.x; f[3] = f1.y;
    f[4] = f2.x; f[5] = f2.y; f[6] = f3.x; f[7] = f3.y;
}

__device__ __forceinline__ void f8_to_hl(const float* a, uint4& hi, uint4& lo) {
    __half2 h0 = __floats2half2_rn(a[0], a[1]);
    __half2 h1 = __floats2half2_rn(a[2], a[3]);
    __half2 h2 = __floats2half2_rn(a[4], a[5]);
    __half2 h3 = __floats2half2_rn(a[6], a[7]);
    float2 g0 = __half22float2(h0), g1 = __half22float2(h1);
    float2 g2 = __half22float2(h2), g3 = __half22float2(h3);
    __half2 l0 = __floats2half2_rn(a[0] - g0.x, a[1] - g0.y);
    __half2 l1 = __floats2half2_rn(a[2] - g1.x, a[3] - g1.y);
    __half2 l2 = __floats2half2_rn(a[4] - g2.x, a[5] - g2.y);
    __half2 l3 = __floats2half2_rn(a[6] - g3.x, a[7] - g3.y);
    hi.x = *(unsigned*)&h0; hi.y = *(unsigned*)&h1;
    hi.z = *(unsigned*)&h2; hi.w = *(unsigned*)&h3;
    lo.x = *(unsigned*)&l0; lo.y = *(unsigned*)&l1;
    lo.z = *(unsigned*)&l2; lo.w = *(unsigned*)&l3;
}

// ---------------- step 0: warp-per-molecule convert + segment mean -----------
__global__ void __launch_bounds__(256) step0_kernel(const float4* __restrict__ F4) {
    int tid  = threadIdx.x;
    int lane = tid & 31;
    int wid  = tid >> 5;
    int b    = blockIdx.x * 8 + wid;
    if (b >= BMOL) return;

    int half_id = lane >> 4;
    int sub     = lane & 15;

    int s = g_segstart[b];
    int e = g_segstart[b + 1];
    int cnt = e - s;

    uint4* xh = (uint4*)g_Xh + (size_t)b * 32;
    uint4* xl = (uint4*)g_Xl + (size_t)b * 32;
    uint4 z4 = make_uint4(0, 0, 0, 0);

    if (cnt <= 0) {
        int o = half_id * 16 + sub;
        xh[o] = z4; xl[o] = z4;
        return;
    }

    float acc[8];
    #pragma unroll
    for (int k = 0; k < 8; k++) acc[k] = 0.f;

    for (int a0 = 0; a0 < cnt; a0 += 2) {
        int a = a0 + half_id;
        if (a < cnt) {
            size_t row = (size_t)(s + a);
            float4 va = F4[row * 32 + sub * 2];
            float4 vb = F4[row * 32 + sub * 2 + 1];
            __half2 h0 = __floats2half2_rn(va.x, va.y);
            __half2 h1 = __floats2half2_rn(va.z, va.w);
            __half2 h2 = __floats2half2_rn(vb.x, vb.y);
            __half2 h3 = __floats2half2_rn(vb.z, vb.w);
            uint4 o;
            o.x = *(unsigned*)&h0; o.y = *(unsigned*)&h1;
            o.z = *(unsigned*)&h2; o.w = *(unsigned*)&h3;
            ((uint4*)g_Fh)[row * 16 + sub] = o;
            acc[0] += va.x; acc[1] += va.y; acc[2] += va.z; acc[3] += va.w;
            acc[4] += vb.x; acc[5] += vb.y; acc[6] += vb.z; acc[7] += vb.w;
        }
    }
    #pragma unroll
    for (int k = 0; k < 8; k++) acc[k] += __shfl_xor_sync(0xffffffffu, acc[k], 16);

    float invc = 1.0f / (float)cnt;
    #pragma unroll
    for (int k = 0; k < 8; k++) acc[k] *= invc;

    if (half_id == 0) {
        xh[sub] = z4; xl[sub] = z4;            // carry = 0
    } else {
        uint4 hi, lo;
        f8_to_hl(acc, hi, lo);
        xh[16 + sub] = hi; xl[16 + sub] = lo;
    }
}

// ---------------- fused LSTM + warp-per-molecule attention -------------------
// Warp owns molecule b. Prologue: per-lane LSTM for dims 4L..4L+3 from g_z and
// g_mem (updates g_mem, produces carry in regs, shfl-gathered for the dots).
// Then online-softmax attention over the segment; writes X (or final out).
__global__ void __launch_bounds__(256) attn_kernel(
    float* __restrict__ out, int final_step, const float4* __restrict__ bias4) {
    int tid  = threadIdx.x;
    int lane = tid & 31;
    int wid  = tid >> 5;
    int b    = blockIdx.x * 8 + wid;
    if (b >= BMOL) return;

    int half_id = lane >> 4;
    int sub     = lane & 15;

    // ---- LSTM prologue: dims j = lane*4 .. lane*4+3 ----
    const float4* zr = (const float4*)(g_z + (size_t)b * 512);
    float4 u4 = zr[lane];
    float4 f4 = zr[32 + lane];
    float4 c4 = zr[64 + lane];
    float4 o4 = zr[96 + lane];
    float4 bu = bias4[lane], bf = bias4[32 + lane],
           bc = bias4[64 + lane], bo = bias4[96 + lane];
    float4 m4 = ((const float4*)g_mem)[(size_t)b * 32 + lane];

    float un[4] = {u4.x + bu.x, u4.y + bu.y, u4.z + bu.z, u4.w + bu.w};
    float fn[4] = {f4.x + bf.x, f4.y + bf.y, f4.z + bf.z, f4.w + bf.w};
    float cn[4] = {c4.x + bc.x, c4.y + bc.y, c4.z + bc.z, c4.w + bc.w};
    float on[4] = {o4.x + bo.x, o4.y + bo.y, o4.z + bo.z, o4.w + bo.w};
    float mm[4] = {m4.x, m4.y, m4.z, m4.w};
    float cy[4];
    #pragma unroll
    for (int k = 0; k < 4; k++) {
        float su = fsigmoid(un[k]);
        float sf = fsigmoid(fn[k]);
        float so = fsigmoid(on[k]);
        float nm = sf * mm[k] + su * ftanh(cn[k]);
        mm[k] = nm;
        cy[k]  = so * ftanh(nm);
    }
    ((float4*)g_mem)[(size_t)b * 32 + lane] = make_float4(mm[0], mm[1], mm[2], mm[3]);

    if (!final_step) {
        // write hi/lo fp16 carry into X (cols lane*4..+3)
        __half2 h01 = __floats2half2_rn(cy[0], cy[1]);
        __half2 h23 = __floats2half2_rn(cy[2], cy[3]);
        float2 g01 = __half22float2(h01), g23 = __half22float2(h23);
        __half2 l01 = __floats2half2_rn(cy[0] - g01.x, cy[1] - g01.y);
        __half2 l23 = __floats2half2_rn(cy[2] - g23.x, cy[3] - g23.y);
        uint2 hv, lv;
        hv.x = *(unsigned*)&h01; hv.y = *(unsigned*)&h23;
        lv.x = *(unsigned*)&l01; lv.y = *(unsigned*)&l23;
        ((uint2*)(g_Xh + (size_t)b * 256))[lane] = hv;
        ((uint2*)(g_Xl + (size_t)b * 256))[lane] = lv;
    }

    // gather carry dims sub*8..sub*8+7 (owned by lanes 2*sub and 2*sub+1)
    float c8[8];
    #pragma unroll
    for (int k = 0; k < 4; k++) {
        c8[k]     = __shfl_sync(0xffffffffu, cy[k], sub * 2);
        c8[4 + k] = __shfl_sync(0xffffffffu, cy[k], sub * 2 + 1);
    }

    // ---- attention over segment ----
    int s = g_segstart[b];
    int e = g_segstart[b + 1];
    int cnt = e - s;

    float m = -INFINITY, ssum = 0.f;
    float acc[8];
    #pragma unroll
    for (int k = 0; k < 8; k++) acc[k] = 0.f;

    const uint4* F4h = (const uint4*)g_Fh;

    if (cnt > 0) {
        int cnt8 = cnt & ~7;
        int a0 = 0;
        for (; a0 < cnt8; a0 += 8) {
            float f[4][8], v[4];
            #pragma unroll
            for (int j = 0; j < 4; j++) {
                int a = a0 + 2 * j + half_id;
                uint4 p = F4h[(size_t)(s + a) * 16 + sub];
                h8_to_f(p, f[j]);
                float vv = 0.f;
                #pragma unroll
                for (int k = 0; k < 8; k++) vv += f[j][k] * c8[k];
                v[j] = vv;
            }
            #pragma unroll
            for (int j = 0; j < 4; j++) {
                #pragma unroll
                for (int o = 8; o > 0; o >>= 1)
                    v[j] += __shfl_xor_sync(0xffffffffu, v[j], o);
            }
            float gm = fmaxf(fmaxf(v[0], v[1]), fmaxf(v[2], v[3]));
            float nm = fmaxf(m, gm);
            float scl = __expf(m - nm);            // 0 on first group (m=-inf)
            float p0 = __expf(v[0] - nm);
            float p1 = __expf(v[1] - nm);
            float p2 = __expf(v[2] - nm);
            float p3 = __expf(v[3] - nm);
            ssum = ssum * scl + ((p0 + p1) + (p2 + p3));
            #pragma unroll
            for (int k = 0; k < 8; k++) {
                float t = acc[k] * scl;
                t += p0 * f[0][k];
                t += p1 * f[1][k];
                t += p2 * f[2][k];
                t += p3 * f[3][k];
                acc[k] = t;
            }
            m = nm;
        }
        for (; a0 < cnt; a0 += 2) {
            int a = a0 + half_id;
            bool valid = (a < cnt);
            float v = 0.f, f[8];
            if (valid) {
                uint4 p = F4h[(size_t)(s + a) * 16 + sub];
                h8_to_f(p, f);
                #pragma unroll
                for (int k = 0; k < 8; k++) v += f[k] * c8[k];
            }
            #pragma unroll
            for (int o = 8; o > 0; o >>= 1) v += __shfl_xor_sync(0xffffffffu, v, o);
            if (valid) {
                float nm   = fmaxf(m, v);
                float scl  = __expf(m - nm);
                float pexp = __expf(v - nm);
                ssum = ssum * scl + pexp;
                #pragma unroll
                for (int k = 0; k < 8; k++) acc[k] = acc[k] * scl + pexp * f[k];
                m = nm;
            }
        }

        // combine half-warps
        float m_o = __shfl_xor_sync(0xffffffffu, m, 16);
        float s_o = __shfl_xor_sync(0xffffffffu, ssum, 16);
        float M2  = fmaxf(m, m_o);
        float sa  = (m   > -INFINITY) ? __expf(m   - M2) : 0.f;
        float sb  = (m_o > -INFINITY) ? __expf(m_o - M2) : 0.f;
        float S    = ssum * sa + s_o * sb;
        float invS = 1.0f / S;
        #pragma unroll
        for (int k = 0; k < 8; k++) {
            float ao = __shfl_xor_sync(0xffffffffu, acc[k], 16);
            acc[k] = (acc[k] * sa + ao * sb) * invS;
        }
    }

    if (final_step) {
        // carry half: each lane writes its own 4 dims
        float* orow = out + (size_t)b * 2 * DIM;
        ((float4*)orow)[lane] = make_float4(cy[0], cy[1], cy[2], cy[3]);
        if (half_id == 1) {
            ((float4*)orow)[32 + sub * 2]     = make_float4(acc[0], acc[1], acc[2], acc[3]);
            ((float4*)orow)[32 + sub * 2 + 1] = make_float4(acc[4], acc[5], acc[6], acc[7]);
        }
    } else if (half_id == 1) {
        uint4 hi, lo;
        f8_to_hl(acc, hi, lo);
        ((uint4*)g_Xh)[(size_t)b * 32 + 16 + sub] = hi;
        ((uint4*)g_Xl)[(size_t)b * 32 + 16 + sub] = lo;
    }
}

// ---------------- cp.async pipelined fp16-split GEMM -------------------------
using namespace nvcuda;
#define GEMM_THREADS 256
#define A_LDH 40
#define B_LDH 136
#define AH_SZ (128 * A_LDH)
#define BH_SZ (32 * B_LDH)
#define STAGE_HALVES (2 * AH_SZ + 2 * BH_SZ)
#define GEMM_SMEM (2 * STAGE_HALVES * sizeof(__half))

__device__ __forceinline__ void cp16(void* smem, const void* gmem) {
    unsigned saddr = (unsigned)__cvta_generic_to_shared(smem);
    asm volatile("cp.async.cg.shared.global [%0], [%1], 16;" :: "r"(saddr), "l"(gmem));
}

__global__ void __launch_bounds__(GEMM_THREADS, 2) gemm_kernel() {
    int bm = blockIdx.x * 128;
    int bn = blockIdx.y * 128;
    int tid = threadIdx.x;

    extern __shared__ __half smh[];

    wmma::fragment<wmma::accumulator, 16, 16, 16, float> acc[2][4];
    #pragma unroll
    for (int i = 0; i < 2; i++)
        #pragma unroll
        for (int j = 0; j < 4; j++) wmma::fill_fragment(acc[i][j], 0.f);

    int wid = tid >> 5;
    int wm = (wid >> 1) * 32;
    int wn = (wid & 1) * 64;

    auto load_stage = [&](int stg, int k0) {
        __half* Ah = smh + stg * STAGE_HALVES;
        __half* Al = Ah + AH_SZ;
        __half* Bh = Al + AH_SZ;
        __half* Bl = Bh + BH_SZ;
        #pragma unroll
        for (int i = tid; i < 512; i += GEMM_THREADS) {   // A: 128x32 halves
            int r = i >> 2, c = i & 3;
            size_t g = (size_t)(bm + r) * 256 + k0 + c * 8;
            cp16(Ah + r * A_LDH + c * 8, g_Xh + g);
            cp16(Al + r * A_LDH + c * 8, g_Xl + g);
        }
        #pragma unroll
        for (int i = tid; i < 512; i += GEMM_THREADS) {   // B: 32x128 halves
            int r = i >> 4, c = i & 15;
            size_t g = (size_t)(k0 + r) * 512 + bn + c * 8;
            cp16(Bh + r * B_LDH + c * 8, g_Wh + g);
            cp16(Bl + r * B_LDH + c * 8, g_Wl + g);
        }
        asm volatile("cp.async.commit_group;");
    };

    load_stage(0, 0);

    for (int ks = 0; ks < 8; ks++) {
        if (ks < 7) {
            load_stage((ks + 1) & 1, (ks + 1) * 32);
            asm volatile("cp.async.wait_group 1;");
        } else {
            asm volatile("cp.async.wait_group 0;");
        }
        __syncthreads();

        __half* Ah = smh + (ks & 1) * STAGE_HALVES;
        __half* Al = Ah + AH_SZ;
        __half* Bh = Al + AH_SZ;
        __half* Bl = Bh + BH_SZ;

        #pragma unroll
        for (int kk = 0; kk < 32; kk += 16) {
            wmma::fragment<wmma::matrix_a, 16, 16, 16, __half, wmma::row_major> ah[2], al[2];
            wmma::fragment<wmma::matrix_b, 16, 16, 16, __half, wmma::row_major> bh[4], bl[4];
            #pragma unroll
            for (int i = 0; i < 2; i++) {
                wmma::load_matrix_sync(ah[i], &Ah[(wm + i * 16) * A_LDH + kk], A_LDH);
                wmma::load_matrix_sync(al[i], &Al[(wm + i * 16) * A_LDH + kk], A_LDH);
            }
            #pragma unroll
            for (int j = 0; j < 4; j++) {
                wmma::load_matrix_sync(bh[j], &Bh[kk * B_LDH + wn + j * 16], B_LDH);
                wmma::load_matrix_sync(bl[j], &Bl[kk * B_LDH + wn + j * 16], B_LDH);
            }
            #pragma unroll
            for (int i = 0; i < 2; i++)
                #pragma unroll
                for (int j = 0; j < 4; j++) {
                    wmma::mma_sync(acc[i][j], ah[i], bh[j], acc[i][j]);
                    wmma::mma_sync(acc[i][j], ah[i], bl[j], acc[i][j]);
                    wmma::mma_sync(acc[i][j], al[i], bh[j], acc[i][j]);
                }
        }
        __syncthreads();
    }

    #pragma unroll
    for (int i = 0; i < 2; i++)
        #pragma unroll
        for (int j = 0; j < 4; j++)
            wmma::store_matrix_sync(&g_z[(size_t)(bm + wm + i * 16) * 512 + bn + wn + j * 16],
                                    acc[i][j], 512, wmma::mem_row_major);
}

// ---------------- launch ----------------
extern "C" void kernel_launch(void* const* d_in, const int* in_sizes, int n_in,
                              void* d_out, int out_size) {
    const float* F    = (const float*)d_in[0];
    const int*   idx  = (const int*)d_in[1];
    const float* W    = (const float*)d_in[2];
    const float* bias = (const float*)d_in[3];
    float* out = (float*)d_out;

    static bool attr_done = false;
    if (!attr_done) {
        cudaFuncSetAttribute(gemm_kernel, cudaFuncAttributeMaxDynamicSharedMemorySize,
                             (int)GEMM_SMEM);
        attr_done = true;
    }

    init_state<<<(BMOL * DIM + 255) / 256, 256>>>();
    seg_start_kernel<<<(BMOL + 1 + 255) / 256, 256>>>(idx);
    wsplit_kernel<<<(256 * 512 + 255) / 256, 256>>>(W);

    dim3 gg(BMOL / 128, 4);

    // t = 0: convert + mean readout (carry == 0)
    step0_kernel<<<BMOL / 8, 256>>>((const float4*)F);

    // steps 1..7: GEMM (X -> z), then fused LSTM+attention
    for (int t = 1; t < STEPS; t++) {
        gemm_kernel<<<gg, GEMM_THREADS, GEMM_SMEM>>>();
        attn_kernel<<<BMOL / 8, 256>>>(out, (t == STEPS - 1) ? 1 : 0,
                                       (const float4*)bias);
    }
}